// round 4
// baseline (speedup 1.0000x reference)
#include <cuda_runtime.h>
#include <math.h>
#include <float.h>

#define NB   8
#define NPT0 4096
#define NQ   1024
#define KNN  16

// ---- scratch layout (float offsets) ----
#define OFF_COOR4   0
#define OFF_COORA4  131072
#define OFF_COORB4  163840
#define OFF_F0      196608
#define OFF_F1      458752
#define OFF_F2      1507328
#define OFF_F3      2031616
#define OFF_Z       2555904
#define OFF_T       4653056
#define OFF_YMAX    6750208
#define OFF_AW      7798784
#define OFF_DW      7806976
#define OFF_MRS     7815168
#define OFF_KNNI    7815232
#define OFF_IDX1    8339520
#define OFF_IDX2    8347712
#define SCRATCH_FLOATS 8355904

__device__ __align__(16) float  g_scratch[SCRATCH_FLOATS];
__device__ double g_stats[64];

// ---- output layout (floats) ----
#define OUT_COOR  0
#define OUT_F     24576
#define OUT_NORM  1073152
#define OUT_PLANE 1097728

// ----------------------------------------------------------------------------
// split x -> coor(float4 with w = |c|^2 in reference op order) + f0 = c@Win^T + b
__global__ void split_kernel(const float* __restrict__ x,
                             const float* __restrict__ Win,
                             const float* __restrict__ bin,
                             float4* __restrict__ coor4,
                             float* __restrict__ f0) {
    int i = blockIdx.x * blockDim.x + threadIdx.x;
    if (i >= NB * NPT0) return;
    const float* xr = x + (size_t)i * 7;
    float cx = xr[0], cy = xr[1], cz = xr[2];
    // |c|^2 exactly as XLA reduce: (x*x + y*y) + z*z, no fma contraction
    float kk = __fadd_rn(__fadd_rn(__fmul_rn(cx, cx), __fmul_rn(cy, cy)),
                         __fmul_rn(cz, cz));
    coor4[i] = make_float4(cx, cy, cz, kk);
    float* fo = f0 + (size_t)i * 8;
#pragma unroll
    for (int o = 0; o < 8; o++) {
        float v = fmaf(Win[o * 3 + 0], cx, bin[o]);
        v = fmaf(Win[o * 3 + 1], cy, v);
        v = fmaf(Win[o * 3 + 2], cz, v);
        fo[o] = v;
    }
}

// A[o,c] = W[o,c], D[o,c] = W[o,C+c] - W[o,c]   (W: COUT x 2C row-major)
__global__ void prep_kernel(const float* __restrict__ W,
                            float* __restrict__ A, float* __restrict__ D,
                            int COUT, int C) {
    int t = blockIdx.x * blockDim.x + threadIdx.x;
    if (t >= COUT * C) return;
    int o = t / C, c = t - o * C;
    float a = W[o * 2 * C + c];
    A[t] = a;
    D[t] = W[o * 2 * C + C + c] - a;
}

// Out[r,o] = sum_c In[r,c] * Wm[o,c]; 32 rows per block, 128 threads
template <int C, int COUT>
__global__ void __launch_bounds__(128) gemm_kernel(const float* __restrict__ In,
                                                   const float* __restrict__ Wm,
                                                   float* __restrict__ Out) {
    constexpr int RB = 32;
    constexpr int CPT = COUT / 16;
    __shared__ __align__(16) float sIn[C][RB];
    __shared__ __align__(16) float sW[C][COUT];
    int tid = threadIdx.x;
    size_t rowBase = (size_t)blockIdx.x * RB;

    for (int t = tid; t < RB * C / 4; t += 128) {
        int r = t / (C / 4), c4 = (t % (C / 4)) * 4;
        float4 v = *reinterpret_cast<const float4*>(In + (rowBase + r) * C + c4);
        sIn[c4 + 0][r] = v.x; sIn[c4 + 1][r] = v.y;
        sIn[c4 + 2][r] = v.z; sIn[c4 + 3][r] = v.w;
    }
    for (int t = tid; t < COUT * C / 4; t += 128) {
        int o = t / (C / 4), c4 = (t % (C / 4)) * 4;
        float4 v = *reinterpret_cast<const float4*>(Wm + (size_t)o * C + c4);
        sW[c4 + 0][o] = v.x; sW[c4 + 1][o] = v.y;
        sW[c4 + 2][o] = v.z; sW[c4 + 3][o] = v.w;
    }
    __syncthreads();

    int rg = tid >> 4, cg = tid & 15;
    float acc[4][CPT];
#pragma unroll
    for (int i = 0; i < 4; i++)
#pragma unroll
        for (int j = 0; j < CPT; j++) acc[i][j] = 0.f;

#pragma unroll 4
    for (int c = 0; c < C; c++) {
        float4 rv4 = *reinterpret_cast<const float4*>(&sIn[c][rg * 4]);
        float rv[4] = {rv4.x, rv4.y, rv4.z, rv4.w};
        float wv[CPT];
#pragma unroll
        for (int j = 0; j < CPT; j++) wv[j] = sW[c][cg * CPT + j];
#pragma unroll
        for (int i = 0; i < 4; i++)
#pragma unroll
            for (int j = 0; j < CPT; j++)
                acc[i][j] = fmaf(rv[i], wv[j], acc[i][j]);
    }
#pragma unroll
    for (int i = 0; i < 4; i++) {
        float* op = Out + (rowBase + rg * 4 + i) * COUT + cg * CPT;
#pragma unroll
        for (int j = 0; j < CPT; j++) op[j] = acc[i][j];
    }
}

// warp-per-query KNN: 16 smallest d2, lowest-index tie break.
// d2 computed EXACTLY like the reference: (|q|^2 - 2*dot) + |k|^2,
// dot as cublas-style fma chain, norms precomputed in coord .w.
__global__ void __launch_bounds__(256) knn_kernel(const float4* __restrict__ cq, int Q,
                                                  const float4* __restrict__ ck, int NC,
                                                  int* __restrict__ idx_out) {
    int w = blockIdx.x * 8 + (threadIdx.x >> 5);
    int lane = threadIdx.x & 31;
    int b = w / Q;
    float4 qp = cq[w];
    float qq = qp.w;
    const float4* ckb = ck + (size_t)b * NC;

    float bd[KNN];
    int   bi[KNN];
#pragma unroll
    for (int j = 0; j < KNN; j++) { bd[j] = FLT_MAX; bi[j] = 0x7fffffff; }

    for (int c = lane; c < NC; c += 32) {
        float4 p = ckb[c];
        // dot = fma(z,z', fma(y,y', rn(x*x')))
        float dot = __fmaf_rn(qp.z, p.z,
                    __fmaf_rn(qp.y, p.y, __fmul_rn(qp.x, p.x)));
        // d2 = (qq - 2*dot) + kk  (reference expression tree)
        float d = __fadd_rn(__fsub_rn(qq, __fmul_rn(2.0f, dot)), p.w);
        if (d < bd[KNN - 1]) {
            float vd = d; int vi = c;
#pragma unroll
            for (int j = 0; j < KNN; j++) {
                if (vd < bd[j]) {
                    float td = bd[j]; int ti = bi[j];
                    bd[j] = vd; bi[j] = vi; vd = td; vi = ti;
                }
            }
        }
    }

    int* outp = idx_out + (size_t)w * KNN;
    for (int r = 0; r < KNN; r++) {
        float mv = bd[0]; int mi = bi[0]; int ml = lane;
#pragma unroll
        for (int off = 16; off > 0; off >>= 1) {
            float ov = __shfl_down_sync(0xffffffffu, mv, off);
            int oi = __shfl_down_sync(0xffffffffu, mi, off);
            int ol = __shfl_down_sync(0xffffffffu, ml, off);
            if (ov < mv || (ov == mv && oi < mi)) { mv = ov; mi = oi; ml = ol; }
        }
        ml = __shfl_sync(0xffffffffu, ml, 0);
        mi = __shfl_sync(0xffffffffu, mi, 0);
        if (lane == 0) outp[r] = mi;
        if (lane == ml) {
#pragma unroll
            for (int j = 0; j < KNN - 1; j++) { bd[j] = bd[j + 1]; bi[j] = bi[j + 1]; }
            bd[KNN - 1] = FLT_MAX; bi[KNN - 1] = 0x7fffffff;
        }
    }
}

__global__ void zero_stats_kernel(double* __restrict__ stats) {
    if (threadIdx.x < 64) stats[threadIdx.x] = 0.0;
}

// y[q,k,o] = Z[nbr[q,k],o] + T[qrow,o]; emit max_k, accumulate GN sum/sumsq
template <int COUT>
__global__ void __launch_bounds__(256) gathermax_kernel(
        const float* __restrict__ Z, const float* __restrict__ Tf,
        const int* __restrict__ nbr, const int* __restrict__ qmap,
        int Q, int NC, float* __restrict__ ymax, double* __restrict__ stats) {
    constexpr int OPL = COUT / 32;
    __shared__ double sacc[8];
    int tid = threadIdx.x;
    if (tid < 8) sacc[tid] = 0.0;
    __syncthreads();

    int w = blockIdx.x * 8 + (tid >> 5);
    int lane = tid & 31;
    int b = w / Q, q = w - b * Q;
    int qr = qmap ? qmap[w] : q;
    const float* Tp = Tf + ((size_t)b * NC + qr) * COUT + lane * OPL;
    const int* ip = nbr + (size_t)w * KNN;

    float tv[OPL], mx[OPL];
    if constexpr (OPL == 1) {
        tv[0] = Tp[0];
    } else if constexpr (OPL == 2) {
        float2 t2 = *reinterpret_cast<const float2*>(Tp);
        tv[0] = t2.x; tv[1] = t2.y;
    } else {
        float4 t4 = *reinterpret_cast<const float4*>(Tp);
        tv[0] = t4.x; tv[1] = t4.y; tv[2] = t4.z; tv[3] = t4.w;
    }
#pragma unroll
    for (int j = 0; j < OPL; j++) mx[j] = -FLT_MAX;

    float s = 0.f, s2 = 0.f;
    const float* Zb = Z + (size_t)b * NC * COUT;

#pragma unroll 4
    for (int k = 0; k < KNN; k++) {
        int id = ip[k];
        const float* zp = Zb + (size_t)id * COUT + lane * OPL;
        float zv[OPL];
        if constexpr (OPL == 1) {
            zv[0] = zp[0];
        } else if constexpr (OPL == 2) {
            float2 t2 = *reinterpret_cast<const float2*>(zp);
            zv[0] = t2.x; zv[1] = t2.y;
        } else {
            float4 t4 = *reinterpret_cast<const float4*>(zp);
            zv[0] = t4.x; zv[1] = t4.y; zv[2] = t4.z; zv[3] = t4.w;
        }
#pragma unroll
        for (int j = 0; j < OPL; j++) {
            float y = zv[j] + tv[j];
            mx[j] = fmaxf(mx[j], y);
            s += y;
            s2 = fmaf(y, y, s2);
        }
    }
    float* yp = ymax + (size_t)w * COUT + lane * OPL;
    if constexpr (OPL == 1) {
        yp[0] = mx[0];
    } else if constexpr (OPL == 2) {
        *reinterpret_cast<float2*>(yp) = make_float2(mx[0], mx[1]);
    } else {
        *reinterpret_cast<float4*>(yp) = make_float4(mx[0], mx[1], mx[2], mx[3]);
    }

    // 8-lane segment reduction (all OPL outputs of a lane share one group)
#pragma unroll
    for (int off = 4; off > 0; off >>= 1) {
        s  += __shfl_down_sync(0xffffffffu, s, off, 8);
        s2 += __shfl_down_sync(0xffffffffu, s2, off, 8);
    }
    if ((lane & 7) == 0) {
        int g = lane >> 3;
        atomicAdd(&sacc[g * 2 + 0], (double)s);
        atomicAdd(&sacc[g * 2 + 1], (double)s2);
    }
    __syncthreads();
    int b0 = (blockIdx.x * 8) / Q;
    if (tid < 8) atomicAdd(&stats[b0 * 8 + tid], sacc[tid]);
}

__global__ void finalize_stats_kernel(const double* __restrict__ stats,
                                      float* __restrict__ mrs, double invcnt) {
    int t = threadIdx.x;
    if (t >= 32) return;
    double s = stats[t * 2], s2 = stats[t * 2 + 1];
    double m = s * invcnt;
    double v = s2 * invcnt - m * m;
    mrs[t * 2 + 0] = (float)m;
    mrs[t * 2 + 1] = (float)(1.0 / sqrt(v + 1e-5));
}

template <int COUT>
__global__ void normalize_kernel(const float* __restrict__ ymax,
                                 const float* __restrict__ mrs,
                                 const float* __restrict__ gw,
                                 const float* __restrict__ gb,
                                 int Q, float* __restrict__ out) {
    int t = blockIdx.x * blockDim.x + threadIdx.x;
    if (t >= NB * Q * COUT) return;
    int o = t % COUT;
    int b = t / (Q * COUT);
    int g = o / (COUT / 4);
    float m = mrs[(b * 4 + g) * 2 + 0];
    float rs = mrs[(b * 4 + g) * 2 + 1];
    float a = fmaf((ymax[t] - m) * rs, gw[o], gb[o]);
    out[t] = a > 0.f ? a : 0.2f * a;
}

// farthest point sampling: one block per batch, coords/dist register-resident.
// Distance op order matches reference reduce: (dx*dx + dy*dy) + dz*dz.
template <int NPTS>
__global__ void __launch_bounds__(256) fps_kernel(const float4* __restrict__ coor,
                                                  int* __restrict__ idx_out) {
    constexpr int TPB = 256;
    constexpr int PPT = NPTS / TPB;
    constexpr int NW = TPB / 32;
    int b = blockIdx.x, tid = threadIdx.x;
    int lane = tid & 31, wid = tid >> 5;
    const float4* cb = coor + (size_t)b * NPTS;

    float px[PPT], py[PPT], pz[PPT], dist[PPT];
#pragma unroll
    for (int i = 0; i < PPT; i++) {
        float4 p = cb[i * TPB + tid];
        px[i] = p.x; py[i] = p.y; pz[i] = p.z;
        dist[i] = FLT_MAX;
    }
    __shared__ float spx, spy, spz;
    __shared__ float swv[NW];
    __shared__ int swi[NW];
    if (tid == 0) {
        idx_out[b * NQ] = 0;
        float4 p0 = cb[0];
        spx = p0.x; spy = p0.y; spz = p0.z;
    }
    __syncthreads();

    for (int it = 1; it < NQ; it++) {
        float bx = spx, by = spy, bz = spz;
        float bestv = -1.f; int besti = 0;
#pragma unroll
        for (int i = 0; i < PPT; i++) {
            float dx = __fsub_rn(px[i], bx);
            float dy = __fsub_rn(py[i], by);
            float dz = __fsub_rn(pz[i], bz);
            float d = __fadd_rn(__fadd_rn(__fmul_rn(dx, dx), __fmul_rn(dy, dy)),
                                __fmul_rn(dz, dz));
            d = fminf(dist[i], d);
            dist[i] = d;
            if (d > bestv) { bestv = d; besti = i * TPB + tid; }
        }
#pragma unroll
        for (int off = 16; off > 0; off >>= 1) {
            float ov = __shfl_down_sync(0xffffffffu, bestv, off);
            int oi = __shfl_down_sync(0xffffffffu, besti, off);
            if (ov > bestv || (ov == bestv && oi < besti)) { bestv = ov; besti = oi; }
        }
        if (lane == 0) { swv[wid] = bestv; swi[wid] = besti; }
        __syncthreads();
        if (tid == 0) {
            float v = swv[0]; int wi = swi[0];
#pragma unroll
            for (int u = 1; u < NW; u++) {
                float uv = swv[u]; int ui = swi[u];
                if (uv > v || (uv == v && ui < wi)) { v = uv; wi = ui; }
            }
            idx_out[b * NQ + it] = wi;
            float4 p = cb[wi];
            spx = p.x; spy = p.y; spz = p.z;
        }
        __syncthreads();
    }
}

__global__ void gather_coor_kernel(const float4* __restrict__ src, int NPTS,
                                   const int* __restrict__ idx,
                                   float4* __restrict__ dst) {
    int t = blockIdx.x * blockDim.x + threadIdx.x;
    if (t >= NB * NQ) return;
    int b = t >> 10;
    dst[t] = src[(size_t)b * NPTS + idx[t]];
}

__global__ void finalize_out_kernel(const float* __restrict__ x,
                                    const float4* __restrict__ coorB,
                                    const int* __restrict__ idx1,
                                    const int* __restrict__ idx2,
                                    float* __restrict__ out) {
    int t = blockIdx.x * blockDim.x + threadIdx.x;
    if (t >= NB * NQ) return;
    int b = t >> 10;
    int row = idx1[(b << 10) + idx2[t]];
    const float* xr = x + ((size_t)b * NPT0 + row) * 7;
    out[OUT_NORM + t * 3 + 0] = xr[3];
    out[OUT_NORM + t * 3 + 1] = xr[4];
    out[OUT_NORM + t * 3 + 2] = xr[5];
    out[OUT_PLANE + t] = xr[6];
    float4 c = coorB[t];
    out[OUT_COOR + t * 3 + 0] = c.x;
    out[OUT_COOR + t * 3 + 1] = c.y;
    out[OUT_COOR + t * 3 + 2] = c.z;
}

// ----------------------------------------------------------------------------
extern "C" void kernel_launch(void* const* d_in, const int* in_sizes, int n_in,
                              void* d_out, int out_size) {
    const float* x   = (const float*)d_in[0];
    const float* Win = (const float*)d_in[1];
    const float* bin = (const float*)d_in[2];
    const float* W1  = (const float*)d_in[3];
    const float* g1w = (const float*)d_in[4];
    const float* g1b = (const float*)d_in[5];
    const float* W2  = (const float*)d_in[6];
    const float* g2w = (const float*)d_in[7];
    const float* g2b = (const float*)d_in[8];
    const float* W3  = (const float*)d_in[9];
    const float* g3w = (const float*)d_in[10];
    const float* g3b = (const float*)d_in[11];
    const float* W4  = (const float*)d_in[12];
    const float* g4w = (const float*)d_in[13];
    const float* g4b = (const float*)d_in[14];
    float* out = (float*)d_out;

    void* sp; cudaGetSymbolAddress(&sp, g_scratch);
    float* S = (float*)sp;
    void* stp; cudaGetSymbolAddress(&stp, g_stats);
    double* stats = (double*)stp;

    float4* coor4  = (float4*)(S + OFF_COOR4);
    float4* coorA4 = (float4*)(S + OFF_COORA4);
    float4* coorB4 = (float4*)(S + OFF_COORB4);
    float* f0  = S + OFF_F0;
    float* f1  = S + OFF_F1;
    float* f2  = S + OFF_F2;
    float* f3  = S + OFF_F3;
    float* Z   = S + OFF_Z;
    float* T   = S + OFF_T;
    float* ym  = S + OFF_YMAX;
    float* A   = S + OFF_AW;
    float* D   = S + OFF_DW;
    float* mrs = S + OFF_MRS;
    int* nbr   = (int*)(S + OFF_KNNI);
    int* idx1  = (int*)(S + OFF_IDX1);
    int* idx2  = (int*)(S + OFF_IDX2);

    split_kernel<<<(NB * NPT0 + 255) / 256, 256>>>(x, Win, bin, coor4, f0);

    // FPS over the 4096-point clouds (needed from layer 2 on)
    fps_kernel<NPT0><<<NB, 256>>>(coor4, idx1);

    // ---- Layer 1: Q=4096, NC=4096, C=8, COUT=32 ----
    prep_kernel<<<2, 128>>>(W1, A, D, 32, 8);
    gemm_kernel<8, 32><<<NB * NPT0 / 32, 128>>>(f0, A, Z);
    gemm_kernel<8, 32><<<NB * NPT0 / 32, 128>>>(f0, D, T);
    knn_kernel<<<NB * NPT0 / 8, 256>>>(coor4, NPT0, coor4, NPT0, nbr);
    zero_stats_kernel<<<1, 64>>>(stats);
    gathermax_kernel<32><<<NB * NPT0 / 8, 256>>>(Z, T, nbr, nullptr, NPT0, NPT0, ym, stats);
    finalize_stats_kernel<<<1, 32>>>(stats, mrs, 1.0 / (4096.0 * 16.0 * 8.0));
    normalize_kernel<32><<<(NB * NPT0 * 32 + 255) / 256, 256>>>(ym, mrs, g1w, g1b, NPT0, f1);

    gather_coor_kernel<<<(NB * NQ + 255) / 256, 256>>>(coor4, NPT0, idx1, coorA4);

    // ---- Layer 2: Q=1024, NC=4096, C=32, COUT=64 ----
    prep_kernel<<<16, 128>>>(W2, A, D, 64, 32);
    gemm_kernel<32, 64><<<NB * NPT0 / 32, 128>>>(f1, A, Z);
    gemm_kernel<32, 64><<<NB * NPT0 / 32, 128>>>(f1, D, T);
    knn_kernel<<<NB * NQ / 8, 256>>>(coorA4, NQ, coor4, NPT0, nbr);
    zero_stats_kernel<<<1, 64>>>(stats);
    gathermax_kernel<64><<<NB * NQ / 8, 256>>>(Z, T, nbr, idx1, NQ, NPT0, ym, stats);
    finalize_stats_kernel<<<1, 32>>>(stats, mrs, 1.0 / (1024.0 * 16.0 * 16.0));
    normalize_kernel<64><<<(NB * NQ * 64 + 255) / 256, 256>>>(ym, mrs, g2w, g2b, NQ, f2);

    // ---- Layer 3: Q=1024, NC=1024, C=64, COUT=64 ----
    prep_kernel<<<32, 128>>>(W3, A, D, 64, 64);
    gemm_kernel<64, 64><<<NB * NQ / 32, 128>>>(f2, A, Z);
    gemm_kernel<64, 64><<<NB * NQ / 32, 128>>>(f2, D, T);
    knn_kernel<<<NB * NQ / 8, 256>>>(coorA4, NQ, coorA4, NQ, nbr);
    zero_stats_kernel<<<1, 64>>>(stats);
    gathermax_kernel<64><<<NB * NQ / 8, 256>>>(Z, T, nbr, nullptr, NQ, NQ, ym, stats);
    finalize_stats_kernel<<<1, 32>>>(stats, mrs, 1.0 / (1024.0 * 16.0 * 16.0));
    normalize_kernel<64><<<(NB * NQ * 64 + 255) / 256, 256>>>(ym, mrs, g3w, g3b, NQ, f3);

    // ---- FPS over the 1024-point clouds ----
    fps_kernel<NQ><<<NB, 256>>>(coorA4, idx2);
    gather_coor_kernel<<<(NB * NQ + 255) / 256, 256>>>(coorA4, NQ, idx2, coorB4);

    // ---- Layer 4: Q=1024, NC=1024, C=64, COUT=128 ----
    prep_kernel<<<64, 128>>>(W4, A, D, 128, 64);
    gemm_kernel<64, 128><<<NB * NQ / 32, 128>>>(f3, A, Z);
    gemm_kernel<64, 128><<<NB * NQ / 32, 128>>>(f3, D, T);
    knn_kernel<<<NB * NQ / 8, 256>>>(coorB4, NQ, coorA4, NQ, nbr);
    zero_stats_kernel<<<1, 64>>>(stats);
    gathermax_kernel<128><<<NB * NQ / 8, 256>>>(Z, T, nbr, idx2, NQ, NQ, ym, stats);
    finalize_stats_kernel<<<1, 32>>>(stats, mrs, 1.0 / (1024.0 * 16.0 * 32.0));
    normalize_kernel<128><<<(NB * NQ * 128 + 255) / 256, 256>>>(ym, mrs, g4w, g4b, NQ, out + OUT_F);

    finalize_out_kernel<<<(NB * NQ + 255) / 256, 256>>>(x, coorB4, idx1, idx2, out);
}

// round 7
// speedup vs baseline: 1.2907x; 1.2907x over previous
#include <cuda_runtime.h>
#include <math.h>
#include <float.h>

#define NB   8
#define NPT0 4096
#define NQ   1024
#define KNN  16

// ---- scratch layout (float offsets) ----
#define OFF_COOR4   0
#define OFF_COORA4  131072
#define OFF_COORB4  163840
#define OFF_F0      196608
#define OFF_F1      458752
#define OFF_F2      1507328
#define OFF_F3      2031616
#define OFF_Z       2555904
#define OFF_T       4653056
#define OFF_YMAX    6750208
#define OFF_AW      7798784
#define OFF_DW      7806976
#define OFF_MRS     7815168
#define OFF_KNNI    7815232
#define OFF_IDX1    8339520
#define OFF_IDX2    8347712
#define SCRATCH_FLOATS 8355904

__device__ __align__(16) float  g_scratch[SCRATCH_FLOATS];
__device__ double g_stats[64];

// ---- output layout (floats) ----
#define OUT_COOR  0
#define OUT_F     24576
#define OUT_NORM  1073152
#define OUT_PLANE 1097728

// ----------------------------------------------------------------------------
__global__ void split_kernel(const float* __restrict__ x,
                             const float* __restrict__ Win,
                             const float* __restrict__ bin,
                             float4* __restrict__ coor4,
                             float* __restrict__ f0) {
    int i = blockIdx.x * blockDim.x + threadIdx.x;
    if (i >= NB * NPT0) return;
    const float* xr = x + (size_t)i * 7;
    float cx = xr[0], cy = xr[1], cz = xr[2];
    float kk = __fadd_rn(__fadd_rn(__fmul_rn(cx, cx), __fmul_rn(cy, cy)),
                         __fmul_rn(cz, cz));
    coor4[i] = make_float4(cx, cy, cz, kk);
    float* fo = f0 + (size_t)i * 8;
#pragma unroll
    for (int o = 0; o < 8; o++) {
        float v = fmaf(Win[o * 3 + 0], cx, bin[o]);
        v = fmaf(Win[o * 3 + 1], cy, v);
        v = fmaf(Win[o * 3 + 2], cz, v);
        fo[o] = v;
    }
}

__global__ void prep_kernel(const float* __restrict__ W,
                            float* __restrict__ A, float* __restrict__ D,
                            int COUT, int C) {
    int t = blockIdx.x * blockDim.x + threadIdx.x;
    if (t >= COUT * C) return;
    int o = t / C, c = t - o * C;
    float a = W[o * 2 * C + c];
    A[t] = a;
    D[t] = W[o * 2 * C + C + c] - a;
}

template <int C, int COUT>
__global__ void __launch_bounds__(128) gemm_kernel(const float* __restrict__ In,
                                                   const float* __restrict__ Wm,
                                                   float* __restrict__ Out) {
    constexpr int RB = 32;
    constexpr int CPT = COUT / 16;
    __shared__ __align__(16) float sIn[C][RB];
    __shared__ __align__(16) float sW[C][COUT];
    int tid = threadIdx.x;
    size_t rowBase = (size_t)blockIdx.x * RB;

    for (int t = tid; t < RB * C / 4; t += 128) {
        int r = t / (C / 4), c4 = (t % (C / 4)) * 4;
        float4 v = *reinterpret_cast<const float4*>(In + (rowBase + r) * C + c4);
        sIn[c4 + 0][r] = v.x; sIn[c4 + 1][r] = v.y;
        sIn[c4 + 2][r] = v.z; sIn[c4 + 3][r] = v.w;
    }
    for (int t = tid; t < COUT * C / 4; t += 128) {
        int o = t / (C / 4), c4 = (t % (C / 4)) * 4;
        float4 v = *reinterpret_cast<const float4*>(Wm + (size_t)o * C + c4);
        sW[c4 + 0][o] = v.x; sW[c4 + 1][o] = v.y;
        sW[c4 + 2][o] = v.z; sW[c4 + 3][o] = v.w;
    }
    __syncthreads();

    int rg = tid >> 4, cg = tid & 15;
    float acc[4][CPT];
#pragma unroll
    for (int i = 0; i < 4; i++)
#pragma unroll
        for (int j = 0; j < CPT; j++) acc[i][j] = 0.f;

#pragma unroll 4
    for (int c = 0; c < C; c++) {
        float4 rv4 = *reinterpret_cast<const float4*>(&sIn[c][rg * 4]);
        float rv[4] = {rv4.x, rv4.y, rv4.z, rv4.w};
        float wv[CPT];
#pragma unroll
        for (int j = 0; j < CPT; j++) wv[j] = sW[c][cg * CPT + j];
#pragma unroll
        for (int i = 0; i < 4; i++)
#pragma unroll
            for (int j = 0; j < CPT; j++)
                acc[i][j] = fmaf(rv[i], wv[j], acc[i][j]);
    }
#pragma unroll
    for (int i = 0; i < 4; i++) {
        float* op = Out + (rowBase + rg * 4 + i) * COUT + cg * CPT;
#pragma unroll
        for (int j = 0; j < CPT; j++) op[j] = acc[i][j];
    }
}

// warp-per-query KNN with shared-memory candidate tiling (8 warps share tiles).
// d2 computed EXACTLY like the reference: (|q|^2 - 2*dot) + |k|^2.
__global__ void __launch_bounds__(256) knn_kernel(const float4* __restrict__ cq, int Q,
                                                  const float4* __restrict__ ck, int NC,
                                                  int* __restrict__ idx_out) {
    __shared__ __align__(16) float4 sc[1024];
    int tid = threadIdx.x;
    int wid = tid >> 5, lane = tid & 31;
    int w = blockIdx.x * 8 + wid;
    int b = w / Q;
    float4 qp = cq[w];
    float qq = qp.w;
    const float4* ckb = ck + (size_t)b * NC;

    float bd[KNN];
    int   bi[KNN];
#pragma unroll
    for (int j = 0; j < KNN; j++) { bd[j] = FLT_MAX; bi[j] = 0x7fffffff; }

    for (int t0 = 0; t0 < NC; t0 += 1024) {
        __syncthreads();
#pragma unroll
        for (int r = 0; r < 4; r++)
            sc[tid + 256 * r] = ckb[t0 + tid + 256 * r];
        __syncthreads();
#pragma unroll 4
        for (int j = lane; j < 1024; j += 32) {
            float4 p = sc[j];
            float dot = __fmaf_rn(qp.z, p.z,
                        __fmaf_rn(qp.y, p.y, __fmul_rn(qp.x, p.x)));
            float d = __fadd_rn(__fsub_rn(qq, __fmul_rn(2.0f, dot)), p.w);
            if (d < bd[KNN - 1]) {
                float vd = d; int vi = t0 + j;
#pragma unroll
                for (int jj = 0; jj < KNN; jj++) {
                    if (vd < bd[jj]) {
                        float td = bd[jj]; int ti = bi[jj];
                        bd[jj] = vd; bi[jj] = vi; vd = td; vi = ti;
                    }
                }
            }
        }
    }

    // merge 32 sorted lists via REDUX (order-preserving fp32 -> u32 key map)
    int* outp = idx_out + (size_t)w * KNN;
    for (int r = 0; r < KNN; r++) {
        unsigned fb = __float_as_uint(bd[0]);
        unsigned key = (fb & 0x80000000u) ? ~fb : (fb | 0x80000000u);
        unsigned mk = __reduce_min_sync(0xffffffffu, key);
        unsigned ci = (key == mk) ? (unsigned)bi[0] : 0xffffffffu;
        unsigned mi = __reduce_min_sync(0xffffffffu, ci);
        if (lane == 0) outp[r] = (int)mi;
        if (key == mk && (unsigned)bi[0] == mi) {
#pragma unroll
            for (int j = 0; j < KNN - 1; j++) { bd[j] = bd[j + 1]; bi[j] = bi[j + 1]; }
            bd[KNN - 1] = FLT_MAX; bi[KNN - 1] = 0x7fffffff;
        }
    }
}

__global__ void zero_stats_kernel(double* __restrict__ stats) {
    if (threadIdx.x < 64) stats[threadIdx.x] = 0.0;
}

template <int COUT>
__global__ void __launch_bounds__(256) gathermax_kernel(
        const float* __restrict__ Z, const float* __restrict__ Tf,
        const int* __restrict__ nbr, const int* __restrict__ qmap,
        int Q, int NC, float* __restrict__ ymax, double* __restrict__ stats) {
    constexpr int OPL = COUT / 32;
    __shared__ double sacc[8];
    int tid = threadIdx.x;
    if (tid < 8) sacc[tid] = 0.0;
    __syncthreads();

    int w = blockIdx.x * 8 + (tid >> 5);
    int lane = tid & 31;
    int b = w / Q, q = w - b * Q;
    int qr = qmap ? qmap[w] : q;
    const float* Tp = Tf + ((size_t)b * NC + qr) * COUT + lane * OPL;
    const int* ip = nbr + (size_t)w * KNN;

    float tv[OPL], mx[OPL];
    if constexpr (OPL == 1) {
        tv[0] = Tp[0];
    } else if constexpr (OPL == 2) {
        float2 t2 = *reinterpret_cast<const float2*>(Tp);
        tv[0] = t2.x; tv[1] = t2.y;
    } else {
        float4 t4 = *reinterpret_cast<const float4*>(Tp);
        tv[0] = t4.x; tv[1] = t4.y; tv[2] = t4.z; tv[3] = t4.w;
    }
#pragma unroll
    for (int j = 0; j < OPL; j++) mx[j] = -FLT_MAX;

    float s = 0.f, s2 = 0.f;
    const float* Zb = Z + (size_t)b * NC * COUT;

#pragma unroll 4
    for (int k = 0; k < KNN; k++) {
        int id = ip[k];
        const float* zp = Zb + (size_t)id * COUT + lane * OPL;
        float zv[OPL];
        if constexpr (OPL == 1) {
            zv[0] = zp[0];
        } else if constexpr (OPL == 2) {
            float2 t2 = *reinterpret_cast<const float2*>(zp);
            zv[0] = t2.x; zv[1] = t2.y;
        } else {
            float4 t4 = *reinterpret_cast<const float4*>(zp);
            zv[0] = t4.x; zv[1] = t4.y; zv[2] = t4.z; zv[3] = t4.w;
        }
#pragma unroll
        for (int j = 0; j < OPL; j++) {
            float y = zv[j] + tv[j];
            mx[j] = fmaxf(mx[j], y);
            s += y;
            s2 = fmaf(y, y, s2);
        }
    }
    float* yp = ymax + (size_t)w * COUT + lane * OPL;
    if constexpr (OPL == 1) {
        yp[0] = mx[0];
    } else if constexpr (OPL == 2) {
        *reinterpret_cast<float2*>(yp) = make_float2(mx[0], mx[1]);
    } else {
        *reinterpret_cast<float4*>(yp) = make_float4(mx[0], mx[1], mx[2], mx[3]);
    }

#pragma unroll
    for (int off = 4; off > 0; off >>= 1) {
        s  += __shfl_down_sync(0xffffffffu, s, off, 8);
        s2 += __shfl_down_sync(0xffffffffu, s2, off, 8);
    }
    if ((lane & 7) == 0) {
        int g = lane >> 3;
        atomicAdd(&sacc[g * 2 + 0], (double)s);
        atomicAdd(&sacc[g * 2 + 1], (double)s2);
    }
    __syncthreads();
    int b0 = (blockIdx.x * 8) / Q;
    if (tid < 8) atomicAdd(&stats[b0 * 8 + tid], sacc[tid]);
}

__global__ void finalize_stats_kernel(const double* __restrict__ stats,
                                      float* __restrict__ mrs, double invcnt) {
    int t = threadIdx.x;
    if (t >= 32) return;
    double s = stats[t * 2], s2 = stats[t * 2 + 1];
    double m = s * invcnt;
    double v = s2 * invcnt - m * m;
    mrs[t * 2 + 0] = (float)m;
    mrs[t * 2 + 1] = (float)(1.0 / sqrt(v + 1e-5));
}

template <int COUT>
__global__ void normalize_kernel(const float* __restrict__ ymax,
                                 const float* __restrict__ mrs,
                                 const float* __restrict__ gw,
                                 const float* __restrict__ gb,
                                 int Q, float* __restrict__ out) {
    int t = blockIdx.x * blockDim.x + threadIdx.x;
    if (t >= NB * Q * COUT) return;
    int o = t % COUT;
    int b = t / (Q * COUT);
    int g = o / (COUT / 4);
    float m = mrs[(b * 4 + g) * 2 + 0];
    float rs = mrs[(b * 4 + g) * 2 + 1];
    float a = fmaf((ymax[t] - m) * rs, gw[o], gb[o]);
    out[t] = a > 0.f ? a : 0.2f * a;
}

// FPS: one block/batch, register-resident coords+dist, REDUX warp argmax,
// single barrier per iteration (double-buffered candidates), L1 pivot reload.
// Distance op order matches reference reduce: (dx*dx + dy*dy) + dz*dz.
template <int NPTS>
__global__ void __launch_bounds__(256) fps_kernel(const float4* __restrict__ coor,
                                                  int* __restrict__ idx_out) {
    constexpr int TPB = 256;
    constexpr int PPT = NPTS / TPB;
    constexpr int NW = TPB / 32;
    int b = blockIdx.x, tid = threadIdx.x;
    int lane = tid & 31, wid = tid >> 5;
    const float4* cb = coor + (size_t)b * NPTS;

    float px[PPT], py[PPT], pz[PPT], dist[PPT];
#pragma unroll
    for (int i = 0; i < PPT; i++) {
        float4 p = cb[i * TPB + tid];
        px[i] = p.x; py[i] = p.y; pz[i] = p.z;
        dist[i] = FLT_MAX;
    }
    __shared__ unsigned long long cand[2][NW];
    if (tid == 0) idx_out[b * NQ] = 0;
    float4 p0 = cb[0];
    float bx = p0.x, by = p0.y, bz = p0.z;

    for (int it = 1; it < NQ; it++) {
        float bestv = -1.f; int besti = 0;
#pragma unroll
        for (int i = 0; i < PPT; i++) {
            float dx = __fsub_rn(px[i], bx);
            float dy = __fsub_rn(py[i], by);
            float dz = __fsub_rn(pz[i], bz);
            float d = __fadd_rn(__fadd_rn(__fmul_rn(dx, dx), __fmul_rn(dy, dy)),
                                __fmul_rn(dz, dz));
            d = fminf(dist[i], d);
            dist[i] = d;
            if (d > bestv) { bestv = d; besti = i * TPB + tid; }
        }
        // warp argmax (values >= 0, so raw fp32 bits are order-preserving)
        unsigned mb = __reduce_max_sync(0xffffffffu, __float_as_uint(bestv));
        unsigned ci = (__float_as_uint(bestv) == mb) ? (unsigned)besti : 0xffffffffu;
        unsigned mi = __reduce_min_sync(0xffffffffu, ci);
        if (lane == 0)
            cand[it & 1][wid] = ((unsigned long long)mb << 32) | (0xffffffffu - mi);
        __syncthreads();
        unsigned long long bestp = cand[it & 1][0];
#pragma unroll
        for (int u = 1; u < NW; u++) {
            unsigned long long c = cand[it & 1][u];
            if (c > bestp) bestp = c;
        }
        int wi = (int)(0xffffffffu - (unsigned)bestp);
        if (tid == 0) idx_out[b * NQ + it] = wi;
        float4 p = cb[wi];   // L1-resident broadcast
        bx = p.x; by = p.y; bz = p.z;
    }
}

__global__ void gather_coor_kernel(const float4* __restrict__ src, int NPTS,
                                   const int* __restrict__ idx,
                                   float4* __restrict__ dst) {
    int t = blockIdx.x * blockDim.x + threadIdx.x;
    if (t >= NB * NQ) return;
    int b = t >> 10;
    dst[t] = src[(size_t)b * NPTS + idx[t]];
}

__global__ void finalize_out_kernel(const float* __restrict__ x,
                                    const float4* __restrict__ coorB,
                                    const int* __restrict__ idx1,
                                    const int* __restrict__ idx2,
                                    float* __restrict__ out) {
    int t = blockIdx.x * blockDim.x + threadIdx.x;
    if (t >= NB * NQ) return;
    int b = t >> 10;
    int row = idx1[(b << 10) + idx2[t]];
    const float* xr = x + ((size_t)b * NPT0 + row) * 7;
    out[OUT_NORM + t * 3 + 0] = xr[3];
    out[OUT_NORM + t * 3 + 1] = xr[4];
    out[OUT_NORM + t * 3 + 2] = xr[5];
    out[OUT_PLANE + t] = xr[6];
    float4 c = coorB[t];
    out[OUT_COOR + t * 3 + 0] = c.x;
    out[OUT_COOR + t * 3 + 1] = c.y;
    out[OUT_COOR + t * 3 + 2] = c.z;
}

// ----------------------------------------------------------------------------
extern "C" void kernel_launch(void* const* d_in, const int* in_sizes, int n_in,
                              void* d_out, int out_size) {
    const float* x   = (const float*)d_in[0];
    const float* Win = (const float*)d_in[1];
    const float* bin = (const float*)d_in[2];
    const float* W1  = (const float*)d_in[3];
    const float* g1w = (const float*)d_in[4];
    const float* g1b = (const float*)d_in[5];
    const float* W2  = (const float*)d_in[6];
    const float* g2w = (const float*)d_in[7];
    const float* g2b = (const float*)d_in[8];
    const float* W3  = (const float*)d_in[9];
    const float* g3w = (const float*)d_in[10];
    const float* g3b = (const float*)d_in[11];
    const float* W4  = (const float*)d_in[12];
    const float* g4w = (const float*)d_in[13];
    const float* g4b = (const float*)d_in[14];
    float* out = (float*)d_out;

    void* sp; cudaGetSymbolAddress(&sp, g_scratch);
    float* S = (float*)sp;
    void* stp; cudaGetSymbolAddress(&stp, g_stats);
    double* stats = (double*)stp;

    float4* coor4  = (float4*)(S + OFF_COOR4);
    float4* coorA4 = (float4*)(S + OFF_COORA4);
    float4* coorB4 = (float4*)(S + OFF_COORB4);
    float* f0  = S + OFF_F0;
    float* f1  = S + OFF_F1;
    float* f2  = S + OFF_F2;
    float* f3  = S + OFF_F3;
    float* Z   = S + OFF_Z;
    float* T   = S + OFF_T;
    float* ym  = S + OFF_YMAX;
    float* A   = S + OFF_AW;
    float* D   = S + OFF_DW;
    float* mrs = S + OFF_MRS;
    int* nbr   = (int*)(S + OFF_KNNI);
    int* idx1  = (int*)(S + OFF_IDX1);
    int* idx2  = (int*)(S + OFF_IDX2);

    split_kernel<<<(NB * NPT0 + 255) / 256, 256>>>(x, Win, bin, coor4, f0);

    fps_kernel<NPT0><<<NB, 256>>>(coor4, idx1);

    // ---- Layer 1: Q=4096, NC=4096, C=8, COUT=32 ----
    prep_kernel<<<2, 128>>>(W1, A, D, 32, 8);
    gemm_kernel<8, 32><<<NB * NPT0 / 32, 128>>>(f0, A, Z);
    gemm_kernel<8, 32><<<NB * NPT0 / 32, 128>>>(f0, D, T);
    knn_kernel<<<NB * NPT0 / 8, 256>>>(coor4, NPT0, coor4, NPT0, nbr);
    zero_stats_kernel<<<1, 64>>>(stats);
    gathermax_kernel<32><<<NB * NPT0 / 8, 256>>>(Z, T, nbr, nullptr, NPT0, NPT0, ym, stats);
    finalize_stats_kernel<<<1, 32>>>(stats, mrs, 1.0 / (4096.0 * 16.0 * 8.0));
    normalize_kernel<32><<<(NB * NPT0 * 32 + 255) / 256, 256>>>(ym, mrs, g1w, g1b, NPT0, f1);

    gather_coor_kernel<<<(NB * NQ + 255) / 256, 256>>>(coor4, NPT0, idx1, coorA4);

    // ---- Layer 2: Q=1024, NC=4096, C=32, COUT=64 ----
    prep_kernel<<<16, 128>>>(W2, A, D, 64, 32);
    gemm_kernel<32, 64><<<NB * NPT0 / 32, 128>>>(f1, A, Z);
    gemm_kernel<32, 64><<<NB * NPT0 / 32, 128>>>(f1, D, T);
    knn_kernel<<<NB * NQ / 8, 256>>>(coorA4, NQ, coor4, NPT0, nbr);
    zero_stats_kernel<<<1, 64>>>(stats);
    gathermax_kernel<64><<<NB * NQ / 8, 256>>>(Z, T, nbr, idx1, NQ, NPT0, ym, stats);
    finalize_stats_kernel<<<1, 32>>>(stats, mrs, 1.0 / (1024.0 * 16.0 * 16.0));
    normalize_kernel<64><<<(NB * NQ * 64 + 255) / 256, 256>>>(ym, mrs, g2w, g2b, NQ, f2);

    // ---- Layer 3: Q=1024, NC=1024, C=64, COUT=64 ----
    prep_kernel<<<32, 128>>>(W3, A, D, 64, 64);
    gemm_kernel<64, 64><<<NB * NQ / 32, 128>>>(f2, A, Z);
    gemm_kernel<64, 64><<<NB * NQ / 32, 128>>>(f2, D, T);
    knn_kernel<<<NB * NQ / 8, 256>>>(coorA4, NQ, coorA4, NQ, nbr);
    zero_stats_kernel<<<1, 64>>>(stats);
    gathermax_kernel<64><<<NB * NQ / 8, 256>>>(Z, T, nbr, nullptr, NQ, NQ, ym, stats);
    finalize_stats_kernel<<<1, 32>>>(stats, mrs, 1.0 / (1024.0 * 16.0 * 16.0));
    normalize_kernel<64><<<(NB * NQ * 64 + 255) / 256, 256>>>(ym, mrs, g3w, g3b, NQ, f3);

    fps_kernel<NQ><<<NB, 256>>>(coorA4, idx2);
    gather_coor_kernel<<<(NB * NQ + 255) / 256, 256>>>(coorA4, NQ, idx2, coorB4);

    // ---- Layer 4: Q=1024, NC=1024, C=64, COUT=128 ----
    prep_kernel<<<64, 128>>>(W4, A, D, 128, 64);
    gemm_kernel<64, 128><<<NB * NQ / 32, 128>>>(f3, A, Z);
    gemm_kernel<64, 128><<<NB * NQ / 32, 128>>>(f3, D, T);
    knn_kernel<<<NB * NQ / 8, 256>>>(coorB4, NQ, coorA4, NQ, nbr);
    zero_stats_kernel<<<1, 64>>>(stats);
    gathermax_kernel<128><<<NB * NQ / 8, 256>>>(Z, T, nbr, idx2, NQ, NQ, ym, stats);
    finalize_stats_kernel<<<1, 32>>>(stats, mrs, 1.0 / (1024.0 * 16.0 * 32.0));
    normalize_kernel<128><<<(NB * NQ * 128 + 255) / 256, 256>>>(ym, mrs, g4w, g4b, NQ, out + OUT_F);

    finalize_out_kernel<<<(NB * NQ + 255) / 256, 256>>>(x, coorB4, idx1, idx2, out);
}